// round 1
// baseline (speedup 1.0000x reference)
#include <cuda_runtime.h>
#include <cstdint>

// Problem constants
constexpr int B_  = 2;
constexpr int T_  = 2048;
constexpr int C_  = 1024;
constexpr int H_  = 16;
constexpr int D_  = 64;
constexpr int C3_ = 3 * C_;   // 3072

// Scratch (allocation-free rule: __device__ globals)
__device__ float g_qkv[(size_t)B_ * T_ * C3_];  // [B,T,3C]
__device__ float g_y  [(size_t)B_ * T_ * C_];   // [B,T,C]

// ---------------------------------------------------------------------------
// GEMM (NT): Cm[m,n] = sum_k A[m,k] * Bm[n,k] + bias[n]
// A: [M,K] row-major, Bm: [N,K] row-major. M%128==0, N%128==0, K%16==0.
// 128x128 tile, BK=16, 256 threads, 8x8 split register tiles.
// ---------------------------------------------------------------------------
__global__ __launch_bounds__(256)
void gemm_nt_bias(const float* __restrict__ A, const float* __restrict__ Bm,
                  const float* __restrict__ bias, float* __restrict__ Cm,
                  int M, int N, int K)
{
    constexpr int BM = 128, BK = 16, SA = BM + 4;
    __shared__ float As[BK][SA];
    __shared__ float Bs[BK][SA];

    const int bm  = blockIdx.y * BM;
    const int bn  = blockIdx.x * BM;
    const int tid = threadIdx.x;
    const int tr  = tid >> 4;    // 0..15
    const int tc  = tid & 15;    // 0..15

    float acc[2][2][4][4];
#pragma unroll
    for (int a = 0; a < 2; a++)
#pragma unroll
        for (int c = 0; c < 2; c++)
#pragma unroll
            for (int i = 0; i < 4; i++)
#pragma unroll
                for (int j = 0; j < 4; j++) acc[a][c][i][j] = 0.f;

    for (int k0 = 0; k0 < K; k0 += BK) {
        // Load 128x16 tiles of A and B (each thread: 2 float4 per array)
#pragma unroll
        for (int p = 0; p < 2; p++) {
            int s   = tid + p * 256;     // 0..511
            int row = s >> 2;            // 0..127
            int kk  = (s & 3) << 2;      // 0,4,8,12
            float4 va = *(const float4*)(A  + (size_t)(bm + row) * K + (k0 + kk));
            As[kk + 0][row] = va.x; As[kk + 1][row] = va.y;
            As[kk + 2][row] = va.z; As[kk + 3][row] = va.w;
            float4 vb = *(const float4*)(Bm + (size_t)(bn + row) * K + (k0 + kk));
            Bs[kk + 0][row] = vb.x; Bs[kk + 1][row] = vb.y;
            Bs[kk + 2][row] = vb.z; Bs[kk + 3][row] = vb.w;
        }
        __syncthreads();

#pragma unroll
        for (int k = 0; k < BK; k++) {
            float a0[4], a1[4], b0[4], b1[4];
            *(float4*)a0 = *(const float4*)&As[k][4 * tr];
            *(float4*)a1 = *(const float4*)&As[k][64 + 4 * tr];
            *(float4*)b0 = *(const float4*)&Bs[k][4 * tc];
            *(float4*)b1 = *(const float4*)&Bs[k][64 + 4 * tc];
#pragma unroll
            for (int i = 0; i < 4; i++)
#pragma unroll
                for (int j = 0; j < 4; j++) {
                    acc[0][0][i][j] = fmaf(a0[i], b0[j], acc[0][0][i][j]);
                    acc[0][1][i][j] = fmaf(a0[i], b1[j], acc[0][1][i][j]);
                    acc[1][0][i][j] = fmaf(a1[i], b0[j], acc[1][0][i][j]);
                    acc[1][1][i][j] = fmaf(a1[i], b1[j], acc[1][1][i][j]);
                }
        }
        __syncthreads();
    }

    // Epilogue: add bias, store float4
#pragma unroll
    for (int rh = 0; rh < 2; rh++)
#pragma unroll
        for (int i = 0; i < 4; i++) {
            int row = bm + rh * 64 + 4 * tr + i;
#pragma unroll
            for (int ch = 0; ch < 2; ch++) {
                int col = bn + ch * 64 + 4 * tc;
                float4 bb = *(const float4*)(bias + col);
                float4 o;
                o.x = acc[rh][ch][i][0] + bb.x;
                o.y = acc[rh][ch][i][1] + bb.y;
                o.z = acc[rh][ch][i][2] + bb.z;
                o.w = acc[rh][ch][i][3] + bb.w;
                *(float4*)(Cm + (size_t)row * N + col) = o;
            }
        }
}

// ---------------------------------------------------------------------------
// Fused causal flash attention (fp32).
// qkv layout: [B, T, 3C] with Q at f = 0*C + h*D + d, K at C + ..., V at 2C + ...
// One CTA handles 64 query rows for one (b,h). Online softmax, base-2 exp.
// smem: Qs[64][68], KVs[64][68] (K transposed then V natural), Ps[64][68].
// ---------------------------------------------------------------------------
constexpr int SD_ = 68;          // padded row stride (floats), 16B aligned
constexpr int ATTN_SMEM = 3 * 64 * SD_ * (int)sizeof(float);  // 52224 bytes

__global__ __launch_bounds__(256)
void attn_fused(const float* __restrict__ qkv, float* __restrict__ y)
{
    extern __shared__ float sm[];
    float (*Qs)[SD_]  = (float (*)[SD_])(sm);
    float (*KVs)[SD_] = (float (*)[SD_])(sm + 64 * SD_);
    float (*Ps)[SD_]  = (float (*)[SD_])(sm + 128 * SD_);
    __shared__ float row_m[64];
    __shared__ float row_l[64];

    // Heavy (late) query blocks first to reduce causal load-imbalance tail.
    const int qb = (int)gridDim.x - 1 - (int)blockIdx.x;
    const int bh = blockIdx.y;
    const int b  = bh >> 4;
    const int h  = bh & 15;
    const int q0 = qb * 64;
    const float* base = qkv + (size_t)b * T_ * C3_;
    const int tid = threadIdx.x;
    const int tr  = tid >> 4;   // 0..15 -> rows 4*tr..4*tr+3
    const int tc  = tid & 15;   // 0..15 -> cols 4*tc..4*tc+3
    const float sc = 0.125f * 1.4426950408889634f;  // (1/sqrt(64)) * log2(e)

    // Load Q tile (coalesced float4)
#pragma unroll
    for (int p = 0; p < 4; p++) {
        int s  = tid + p * 256;
        int r  = s >> 4;
        int c4 = (s & 15) << 2;
        float4 v = *(const float4*)(base + (size_t)(q0 + r) * C3_ + h * D_ + c4);
        *(float4*)&Qs[r][c4] = v;
    }
    if (tid < 64) { row_m[tid] = -1e30f; row_l[tid] = 0.f; }

    float acc[4][4];
#pragma unroll
    for (int i = 0; i < 4; i++)
#pragma unroll
        for (int j = 0; j < 4; j++) acc[i][j] = 0.f;

    for (int j0 = 0; j0 <= q0; j0 += 64) {
        __syncthreads();  // prior PV done reading KVs/Ps; first iter: Q + stats ready

        // Load K block TRANSPOSED: KVs[d][key]. Conflict-free STS (lane -> key).
#pragma unroll
        for (int p = 0; p < 4; p++) {
            int s  = tid + p * 256;
            int r  = s & 63;            // key
            int c4 = (s >> 6) << 2;     // d
            float4 v = *(const float4*)(base + (size_t)(j0 + r) * C3_ + C_ + h * D_ + c4);
            KVs[c4 + 0][r] = v.x; KVs[c4 + 1][r] = v.y;
            KVs[c4 + 2][r] = v.z; KVs[c4 + 3][r] = v.w;
        }
        __syncthreads();

        // S = Q @ K^T  (64x64x64, k-unrolled x4, all float4 LDS)
        float s4[4][4];
#pragma unroll
        for (int i = 0; i < 4; i++)
#pragma unroll
            for (int j = 0; j < 4; j++) s4[i][j] = 0.f;

#pragma unroll
        for (int kk = 0; kk < D_; kk += 4) {
            float a[4][4], bt[4][4];
#pragma unroll
            for (int i = 0; i < 4; i++)
                *(float4*)a[i] = *(const float4*)&Qs[4 * tr + i][kk];
#pragma unroll
            for (int kq = 0; kq < 4; kq++)
                *(float4*)bt[kq] = *(const float4*)&KVs[kk + kq][4 * tc];
#pragma unroll
            for (int kq = 0; kq < 4; kq++)
#pragma unroll
                for (int i = 0; i < 4; i++)
#pragma unroll
                    for (int j = 0; j < 4; j++)
                        s4[i][j] = fmaf(a[i][kq], bt[kq][j], s4[i][j]);
        }

        // Scale (+log2e) and causal mask (only on the diagonal block)
        const bool diag = (j0 == q0);
#pragma unroll
        for (int i = 0; i < 4; i++)
#pragma unroll
            for (int j = 0; j < 4; j++) {
                float v = s4[i][j] * sc;
                if (diag && (4 * tc + j) > (4 * tr + i)) v = -1e30f;
                s4[i][j] = v;
            }

        // Online softmax per row (16 threads per row within one warp half)
        float alpha[4];
#pragma unroll
        for (int i = 0; i < 4; i++) {
            float mx = fmaxf(fmaxf(s4[i][0], s4[i][1]), fmaxf(s4[i][2], s4[i][3]));
            mx = fmaxf(mx, __shfl_xor_sync(0xffffffffu, mx, 1));
            mx = fmaxf(mx, __shfl_xor_sync(0xffffffffu, mx, 2));
            mx = fmaxf(mx, __shfl_xor_sync(0xffffffffu, mx, 4));
            mx = fmaxf(mx, __shfl_xor_sync(0xffffffffu, mx, 8));
            const int r = 4 * tr + i;
            float m_old = row_m[r];
            float m_new = fmaxf(m_old, mx);
            float rs = 0.f;
#pragma unroll
            for (int j = 0; j < 4; j++) {
                float pv = exp2f(s4[i][j] - m_new);
                s4[i][j] = pv;
                rs += pv;
            }
            rs += __shfl_xor_sync(0xffffffffu, rs, 1);
            rs += __shfl_xor_sync(0xffffffffu, rs, 2);
            rs += __shfl_xor_sync(0xffffffffu, rs, 4);
            rs += __shfl_xor_sync(0xffffffffu, rs, 8);
            alpha[i] = exp2f(m_old - m_new);
            if (tc == 0) {               // shuffles above converge warp: safe ordering
                row_m[r] = m_new;
                row_l[r] = row_l[r] * alpha[i] + rs;
            }
        }

        // Write P to smem; rescale O accumulator
#pragma unroll
        for (int i = 0; i < 4; i++) {
            float4 v = make_float4(s4[i][0], s4[i][1], s4[i][2], s4[i][3]);
            *(float4*)&Ps[4 * tr + i][4 * tc] = v;
        }
#pragma unroll
        for (int i = 0; i < 4; i++)
#pragma unroll
            for (int j = 0; j < 4; j++) acc[i][j] *= alpha[i];

        __syncthreads();  // Ps visible; KVs (K) fully consumed -> safe to overwrite

        // Load V block natural layout: KVs[key][d] (coalesced float4)
#pragma unroll
        for (int p = 0; p < 4; p++) {
            int s  = tid + p * 256;
            int r  = s >> 4;
            int c4 = (s & 15) << 2;
            float4 v = *(const float4*)(base + (size_t)(j0 + r) * C3_ + 2 * C_ + h * D_ + c4);
            *(float4*)&KVs[r][c4] = v;
        }
        __syncthreads();

        // O += P @ V
#pragma unroll
        for (int kk = 0; kk < 64; kk += 4) {
            float pp[4][4], vv[4][4];
#pragma unroll
            for (int i = 0; i < 4; i++)
                *(float4*)pp[i] = *(const float4*)&Ps[4 * tr + i][kk];
#pragma unroll
            for (int kq = 0; kq < 4; kq++)
                *(float4*)vv[kq] = *(const float4*)&KVs[kk + kq][4 * tc];
#pragma unroll
            for (int kq = 0; kq < 4; kq++)
#pragma unroll
                for (int i = 0; i < 4; i++)
#pragma unroll
                    for (int j = 0; j < 4; j++)
                        acc[i][j] = fmaf(pp[i][kq], vv[kq][j], acc[i][j]);
        }
    }

    // Epilogue: divide by l, store to y[b, q0+r, h*D + col]
#pragma unroll
    for (int i = 0; i < 4; i++) {
        const int r = 4 * tr + i;
        float inv = 1.0f / row_l[r];
        float4 o = make_float4(acc[i][0] * inv, acc[i][1] * inv,
                               acc[i][2] * inv, acc[i][3] * inv);
        *(float4*)(y + ((size_t)b * T_ + q0 + r) * C_ + h * D_ + 4 * tc) = o;
    }
}

// ---------------------------------------------------------------------------
extern "C" void kernel_launch(void* const* d_in, const int* in_sizes, int n_in,
                              void* d_out, int out_size)
{
    const float* x      = (const float*)d_in[0];   // [B,T,C]
    const float* w_attn = (const float*)d_in[1];   // [3C,C]
    const float* b_attn = (const float*)d_in[2];   // [3C]
    const float* w_proj = (const float*)d_in[3];   // [C,C]
    const float* b_proj = (const float*)d_in[4];   // [C]
    float* out = (float*)d_out;                    // [B,T,C]

    float* qkv = nullptr;
    float* yb  = nullptr;
    cudaGetSymbolAddress((void**)&qkv, g_qkv);
    cudaGetSymbolAddress((void**)&yb,  g_y);

    // Allow >48KB dynamic smem for the attention kernel (idempotent, host-side)
    cudaFuncSetAttribute(attn_fused, cudaFuncAttributeMaxDynamicSharedMemorySize,
                         ATTN_SMEM);

    const int M = B_ * T_;   // 4096

    // 1) QKV projection: [4096,3072] = x[4096,1024] @ w_attn^T + b_attn
    {
        dim3 grid(C3_ / 128, M / 128);
        gemm_nt_bias<<<grid, 256>>>(x, w_attn, b_attn, qkv, M, C3_, C_);
    }

    // 2) Fused causal attention -> g_y
    {
        dim3 grid(T_ / 64, B_ * H_);
        attn_fused<<<grid, 256, ATTN_SMEM>>>(qkv, yb);
    }

    // 3) Output projection: out = y @ w_proj^T + b_proj
    {
        dim3 grid(C_ / 128, M / 128);
        gemm_nt_bias<<<grid, 256>>>(yb, w_proj, b_proj, out, M, C_, C_);
    }
}

// round 3
// speedup vs baseline: 1.3898x; 1.3898x over previous
#include <cuda_runtime.h>
#include <cuda_bf16.h>
#include <cstdint>

// Problem constants
constexpr int B_  = 2;
constexpr int T_  = 2048;
constexpr int C_  = 1024;
constexpr int H_  = 16;
constexpr int D_  = 64;
constexpr int C3_ = 3 * C_;   // 3072
constexpr int M_  = B_ * T_;  // 4096

// Scratch (allocation-free rule: __device__ globals)
__device__ float g_qkv[(size_t)B_ * T_ * C3_];  // [B,T,3C]
__device__ float g_y  [(size_t)B_ * T_ * C_];   // [B,T,C]
__device__ __nv_bfloat16 g_x_hi [(size_t)M_  * C_];
__device__ __nv_bfloat16 g_x_lo [(size_t)M_  * C_];
__device__ __nv_bfloat16 g_wa_hi[(size_t)C3_ * C_];
__device__ __nv_bfloat16 g_wa_lo[(size_t)C3_ * C_];
__device__ __nv_bfloat16 g_wp_hi[(size_t)C_  * C_];
__device__ __nv_bfloat16 g_wp_lo[(size_t)C_  * C_];
__device__ __nv_bfloat16 g_y_hi [(size_t)M_  * C_];
__device__ __nv_bfloat16 g_y_lo [(size_t)M_  * C_];

// ---------------------------------------------------------------------------
// Baseline-PTX helpers (sm_80+ instructions only — no 'a'-feature tcgen05)
// ---------------------------------------------------------------------------
__device__ __forceinline__ uint32_t smem_u32(const void* p) {
    uint32_t a;
    asm("{ .reg .u64 t; cvta.to.shared.u64 t, %1; cvt.u32.u64 %0, t; }"
        : "=r"(a) : "l"(p));
    return a;
}

__device__ __forceinline__ void cp_async16(uint32_t saddr, const void* gaddr) {
    asm volatile("cp.async.cg.shared.global [%0], [%1], 16;"
                 :: "r"(saddr), "l"(gaddr) : "memory");
}
__device__ __forceinline__ void cp_commit() {
    asm volatile("cp.async.commit_group;" ::: "memory");
}
template <int N>
__device__ __forceinline__ void cp_wait() {
    asm volatile("cp.async.wait_group %0;" :: "n"(N) : "memory");
}

__device__ __forceinline__ void ldsm_x4(uint32_t& r0, uint32_t& r1,
                                        uint32_t& r2, uint32_t& r3, uint32_t addr) {
    asm volatile("ldmatrix.sync.aligned.m8n8.x4.shared.b16 {%0,%1,%2,%3}, [%4];"
                 : "=r"(r0), "=r"(r1), "=r"(r2), "=r"(r3) : "r"(addr));
}

__device__ __forceinline__ void mma16816(float* d, const uint32_t* a, const uint32_t* b) {
    asm volatile(
        "mma.sync.aligned.m16n8k16.row.col.f32.bf16.bf16.f32 "
        "{%0,%1,%2,%3}, {%4,%5,%6,%7}, {%8,%9}, {%0,%1,%2,%3};"
        : "+f"(d[0]), "+f"(d[1]), "+f"(d[2]), "+f"(d[3])
        : "r"(a[0]), "r"(a[1]), "r"(a[2]), "r"(a[3]), "r"(b[0]), "r"(b[1]));
}

// ---------------------------------------------------------------------------
// fp32 -> bf16 hi/lo split
// ---------------------------------------------------------------------------
__global__ __launch_bounds__(256)
void split_bf16(const float* __restrict__ in, __nv_bfloat16* __restrict__ hi,
                __nv_bfloat16* __restrict__ lo, int n4)
{
    int i = blockIdx.x * blockDim.x + threadIdx.x;
    if (i >= n4) return;
    float4 v = ((const float4*)in)[i];
    __nv_bfloat16 h0 = __float2bfloat16(v.x), h1 = __float2bfloat16(v.y);
    __nv_bfloat16 h2 = __float2bfloat16(v.z), h3 = __float2bfloat16(v.w);
    __nv_bfloat16 l0 = __float2bfloat16(v.x - __bfloat162float(h0));
    __nv_bfloat16 l1 = __float2bfloat16(v.y - __bfloat162float(h1));
    __nv_bfloat16 l2 = __float2bfloat16(v.z - __bfloat162float(h2));
    __nv_bfloat16 l3 = __float2bfloat16(v.w - __bfloat162float(h3));
    ((__nv_bfloat162*)hi)[2 * i + 0] = __nv_bfloat162(h0, h1);
    ((__nv_bfloat162*)hi)[2 * i + 1] = __nv_bfloat162(h2, h3);
    ((__nv_bfloat162*)lo)[2 * i + 0] = __nv_bfloat162(l0, l1);
    ((__nv_bfloat162*)lo)[2 * i + 1] = __nv_bfloat162(l2, l3);
}

// ---------------------------------------------------------------------------
// HMMA GEMM (NT): Cm[m,n] = sum_k A[m,k]*B[n,k] + bias[n]  (fp32 via bf16 split,
// 3 products hi*hi + hi*lo + lo*hi). CTA 128x128, BK=32, 8 warps (2x4),
// warp tile 64x32, cp.async double buffer, padded smem stride 40 bf16 (80B).
// ---------------------------------------------------------------------------
constexpr int BK_   = 32;
constexpr int SKS_  = 40;                       // smem row stride in bf16 (80B)
constexpr int MAT_E = 128 * SKS_;               // elems per matrix tile
constexpr int STAGE_E = 4 * MAT_E;              // Ah, Al, Bh, Bl
constexpr int GEMM_SMEM = 2 * STAGE_E * 2;      // bytes (double buffer, bf16)

__device__ __forceinline__ void stage_loads(uint32_t sbuf,
    const __nv_bfloat16* Ahi, const __nv_bfloat16* Alo,
    const __nv_bfloat16* Bhi, const __nv_bfloat16* Blo,
    int bm, int bn, int k0, int K, int tid)
{
    const __nv_bfloat16* srcs[4] = { Ahi, Alo, Bhi, Blo };
    const int r0s[4] = { bm, bm, bn, bn };
#pragma unroll
    for (int m = 0; m < 4; m++) {
        uint32_t mbase = sbuf + m * MAT_E * 2;
#pragma unroll
        for (int j = 0; j < 2; j++) {
            int s   = tid + j * 256;         // 0..511
            int row = s >> 2;                // 0..127
            int cb  = (s & 3) * 8;           // bf16 col: 0,8,16,24
            const void* g = srcs[m] + (size_t)(r0s[m] + row) * K + k0 + cb;
            cp_async16(mbase + (row * SKS_ + cb) * 2, g);
        }
    }
    cp_commit();
}

__global__ __launch_bounds__(256, 1)
void gemm_mma(const __nv_bfloat16* __restrict__ Ahi, const __nv_bfloat16* __restrict__ Alo,
              const __nv_bfloat16* __restrict__ Bhi, const __nv_bfloat16* __restrict__ Blo,
              const float* __restrict__ bias, float* __restrict__ Cm,
              int M, int N, int K)
{
    extern __shared__ __align__(128) __nv_bfloat16 smem[];
    const int tid  = threadIdx.x;
    const int wid  = tid >> 5;
    const int lane = tid & 31;
    const int wm   = wid >> 2;        // 0..1  (64 rows each)
    const int wn   = wid & 3;         // 0..3  (32 cols each)
    const int bm   = blockIdx.y * 128;
    const int bn   = blockIdx.x * 128;
    const uint32_t sbase = smem_u32(smem);

    float acc[4][4][4];
#pragma unroll
    for (int i = 0; i < 4; i++)
#pragma unroll
        for (int j = 0; j < 4; j++)
#pragma unroll
            for (int r = 0; r < 4; r++) acc[i][j][r] = 0.f;

    // Precomputed ldmatrix lane addresses (element offsets within a matrix tile)
    // A: row = wm*64 + mt*16 + (lane&15), col = (lane>>4)*8 + ks*16
    const int a_row = wm * 64 + (lane & 15);
    const int a_col = (lane >> 4) * 8;
    // B: row(n) = wn*32 + np*16 + ((lane>>4)&1)*8 + (lane&7), col = ((lane>>3)&1)*8 + ks*16
    const int b_row = wn * 32 + ((lane >> 4) & 1) * 8 + (lane & 7);
    const int b_col = ((lane >> 3) & 1) * 8;

    const int S = K / BK_;
    stage_loads(sbase, Ahi, Alo, Bhi, Blo, bm, bn, 0, K, tid);

    for (int s = 0; s < S; s++) {
        if (s + 1 < S)
            stage_loads(sbase + ((s + 1) & 1) * STAGE_E * 2,
                        Ahi, Alo, Bhi, Blo, bm, bn, (s + 1) * BK_, K, tid);
        if (s + 1 < S) cp_wait<1>(); else cp_wait<0>();
        __syncthreads();

        const uint32_t sb  = sbase + (s & 1) * STAGE_E * 2;
        const uint32_t sAh = sb;
        const uint32_t sAl = sb + MAT_E * 2;
        const uint32_t sBh = sb + 2 * MAT_E * 2;
        const uint32_t sBl = sb + 3 * MAT_E * 2;

#pragma unroll
        for (int ks = 0; ks < 2; ks++) {
            uint32_t ah[4][4], al[4][4], bh[2][4], bl[2][4];
            const int ac = a_col + ks * 16;
            const int bc = b_col + ks * 16;
#pragma unroll
            for (int mt = 0; mt < 4; mt++) {
                uint32_t ra = ((a_row + mt * 16) * SKS_ + ac) * 2;
                ldsm_x4(ah[mt][0], ah[mt][1], ah[mt][2], ah[mt][3], sAh + ra);
                ldsm_x4(al[mt][0], al[mt][1], al[mt][2], al[mt][3], sAl + ra);
            }
#pragma unroll
            for (int np = 0; np < 2; np++) {
                uint32_t rb = ((b_row + np * 16) * SKS_ + bc) * 2;
                ldsm_x4(bh[np][0], bh[np][1], bh[np][2], bh[np][3], sBh + rb);
                ldsm_x4(bl[np][0], bl[np][1], bl[np][2], bl[np][3], sBl + rb);
            }
#pragma unroll
            for (int mt = 0; mt < 4; mt++)
#pragma unroll
                for (int nt = 0; nt < 4; nt++) {
                    const uint32_t* bhp = &bh[nt >> 1][(nt & 1) * 2];
                    const uint32_t* blp = &bl[nt >> 1][(nt & 1) * 2];
                    mma16816(acc[mt][nt], ah[mt], bhp);
                    mma16816(acc[mt][nt], ah[mt], blp);
                    mma16816(acc[mt][nt], al[mt], bhp);
                }
        }
        __syncthreads();
    }

    // Epilogue: add bias, store float2 per fragment row
    const int er = lane >> 2;          // 0..7
    const int ec = (lane & 3) * 2;     // 0,2,4,6
#pragma unroll
    for (int mt = 0; mt < 4; mt++) {
        const int row0 = bm + wm * 64 + mt * 16 + er;
#pragma unroll
        for (int nt = 0; nt < 4; nt++) {
            const int col = bn + wn * 32 + nt * 8 + ec;
            const float bx = bias[col], by = bias[col + 1];
            float2 v0 = make_float2(acc[mt][nt][0] + bx, acc[mt][nt][1] + by);
            float2 v1 = make_float2(acc[mt][nt][2] + bx, acc[mt][nt][3] + by);
            *(float2*)(Cm + (size_t)row0 * N + col)       = v0;
            *(float2*)(Cm + (size_t)(row0 + 8) * N + col) = v1;
        }
    }
}

// ---------------------------------------------------------------------------
// Fused causal flash attention (fp32) — unchanged from R1.
// ---------------------------------------------------------------------------
constexpr int SD_ = 68;
constexpr int ATTN_SMEM = 3 * 64 * SD_ * (int)sizeof(float);

__global__ __launch_bounds__(256)
void attn_fused(const float* __restrict__ qkv, float* __restrict__ y)
{
    extern __shared__ float sm[];
    float (*Qs)[SD_]  = (float (*)[SD_])(sm);
    float (*KVs)[SD_] = (float (*)[SD_])(sm + 64 * SD_);
    float (*Ps)[SD_]  = (float (*)[SD_])(sm + 128 * SD_);
    __shared__ float row_m[64];
    __shared__ float row_l[64];

    const int qb = (int)gridDim.x - 1 - (int)blockIdx.x;
    const int bh = blockIdx.y;
    const int b  = bh >> 4;
    const int h  = bh & 15;
    const int q0 = qb * 64;
    const float* base = qkv + (size_t)b * T_ * C3_;
    const int tid = threadIdx.x;
    const int tr  = tid >> 4;
    const int tc  = tid & 15;
    const float sc = 0.125f * 1.4426950408889634f;

#pragma unroll
    for (int p = 0; p < 4; p++) {
        int s  = tid + p * 256;
        int r  = s >> 4;
        int c4 = (s & 15) << 2;
        float4 v = *(const float4*)(base + (size_t)(q0 + r) * C3_ + h * D_ + c4);
        *(float4*)&Qs[r][c4] = v;
    }
    if (tid < 64) { row_m[tid] = -1e30f; row_l[tid] = 0.f; }

    float acc[4][4];
#pragma unroll
    for (int i = 0; i < 4; i++)
#pragma unroll
        for (int j = 0; j < 4; j++) acc[i][j] = 0.f;

    for (int j0 = 0; j0 <= q0; j0 += 64) {
        __syncthreads();
#pragma unroll
        for (int p = 0; p < 4; p++) {
            int s  = tid + p * 256;
            int r  = s & 63;
            int c4 = (s >> 6) << 2;
            float4 v = *(const float4*)(base + (size_t)(j0 + r) * C3_ + C_ + h * D_ + c4);
            KVs[c4 + 0][r] = v.x; KVs[c4 + 1][r] = v.y;
            KVs[c4 + 2][r] = v.z; KVs[c4 + 3][r] = v.w;
        }
        __syncthreads();

        float s4[4][4];
#pragma unroll
        for (int i = 0; i < 4; i++)
#pragma unroll
            for (int j = 0; j < 4; j++) s4[i][j] = 0.f;

#pragma unroll
        for (int kk = 0; kk < D_; kk += 4) {
            float a[4][4], bt[4][4];
#pragma unroll
            for (int i = 0; i < 4; i++)
                *(float4*)a[i] = *(const float4*)&Qs[4 * tr + i][kk];
#pragma unroll
            for (int kq = 0; kq < 4; kq++)
                *(float4*)bt[kq] = *(const float4*)&KVs[kk + kq][4 * tc];
#pragma unroll
            for (int kq = 0; kq < 4; kq++)
#pragma unroll
                for (int i = 0; i < 4; i++)
#pragma unroll
                    for (int j = 0; j < 4; j++)
                        s4[i][j] = fmaf(a[i][kq], bt[kq][j], s4[i][j]);
        }

        const bool diag = (j0 == q0);
#pragma unroll
        for (int i = 0; i < 4; i++)
#pragma unroll
            for (int j = 0; j < 4; j++) {
                float v = s4[i][j] * sc;
                if (diag && (4 * tc + j) > (4 * tr + i)) v = -1e30f;
                s4[i][j] = v;
            }

        float alpha[4];
#pragma unroll
        for (int i = 0; i < 4; i++) {
            float mx = fmaxf(fmaxf(s4[i][0], s4[i][1]), fmaxf(s4[i][2], s4[i][3]));
            mx = fmaxf(mx, __shfl_xor_sync(0xffffffffu, mx, 1));
            mx = fmaxf(mx, __shfl_xor_sync(0xffffffffu, mx, 2));
            mx = fmaxf(mx, __shfl_xor_sync(0xffffffffu, mx, 4));
            mx = fmaxf(mx, __shfl_xor_sync(0xffffffffu, mx, 8));
            const int r = 4 * tr + i;
            float m_old = row_m[r];
            float m_new = fmaxf(m_old, mx);
            float rs = 0.f;
#pragma unroll
            for (int j = 0; j < 4; j++) {
                float pv = exp2f(s4[i][j] - m_new);
                s4[i][j] = pv;
                rs += pv;
            }
            rs += __shfl_xor_sync(0xffffffffu, rs, 1);
            rs += __shfl_xor_sync(0xffffffffu, rs, 2);
            rs += __shfl_xor_sync(0xffffffffu, rs, 4);
            rs += __shfl_xor_sync(0xffffffffu, rs, 8);
            alpha[i] = exp2f(m_old - m_new);
            if (tc == 0) {
                row_m[r] = m_new;
                row_l[r] = row_l[r] * alpha[i] + rs;
            }
        }

#pragma unroll
        for (int i = 0; i < 4; i++) {
            float4 v = make_float4(s4[i][0], s4[i][1], s4[i][2], s4[i][3]);
            *(float4*)&Ps[4 * tr + i][4 * tc] = v;
        }
#pragma unroll
        for (int i = 0; i < 4; i++)
#pragma unroll
            for (int j = 0; j < 4; j++) acc[i][j] *= alpha[i];

        __syncthreads();

#pragma unroll
        for (int p = 0; p < 4; p++) {
            int s  = tid + p * 256;
            int r  = s >> 4;
            int c4 = (s & 15) << 2;
            float4 v = *(const float4*)(base + (size_t)(j0 + r) * C3_ + 2 * C_ + h * D_ + c4);
            *(float4*)&KVs[r][c4] = v;
        }
        __syncthreads();

#pragma unroll
        for (int kk = 0; kk < 64; kk += 4) {
            float pp[4][4], vv[4][4];
#pragma unroll
            for (int i = 0; i < 4; i++)
                *(float4*)pp[i] = *(const float4*)&Ps[4 * tr + i][kk];
#pragma unroll
            for (int kq = 0; kq < 4; kq++)
                *(float4*)vv[kq] = *(const float4*)&KVs[kk + kq][4 * tc];
#pragma unroll
            for (int kq = 0; kq < 4; kq++)
#pragma unroll
                for (int i = 0; i < 4; i++)
#pragma unroll
                    for (int j = 0; j < 4; j++)
                        acc[i][j] = fmaf(pp[i][kq], vv[kq][j], acc[i][j]);
        }
    }

#pragma unroll
    for (int i = 0; i < 4; i++) {
        const int r = 4 * tr + i;
        float inv = 1.0f / row_l[r];
        float4 o = make_float4(acc[i][0] * inv, acc[i][1] * inv,
                               acc[i][2] * inv, acc[i][3] * inv);
        *(float4*)(y + ((size_t)b * T_ + q0 + r) * C_ + h * D_ + 4 * tc) = o;
    }
}

// ---------------------------------------------------------------------------
extern "C" void kernel_launch(void* const* d_in, const int* in_sizes, int n_in,
                              void* d_out, int out_size)
{
    const float* x      = (const float*)d_in[0];
    const float* w_attn = (const float*)d_in[1];
    const float* b_attn = (const float*)d_in[2];
    const float* w_proj = (const float*)d_in[3];
    const float* b_proj = (const float*)d_in[4];
    float* out = (float*)d_out;

    float *qkv = nullptr, *yb = nullptr;
    __nv_bfloat16 *xh, *xl, *wah, *wal, *wph, *wpl, *yh, *yl;
    cudaGetSymbolAddress((void**)&qkv, g_qkv);
    cudaGetSymbolAddress((void**)&yb,  g_y);
    cudaGetSymbolAddress((void**)&xh,  g_x_hi);
    cudaGetSymbolAddress((void**)&xl,  g_x_lo);
    cudaGetSymbolAddress((void**)&wah, g_wa_hi);
    cudaGetSymbolAddress((void**)&wal, g_wa_lo);
    cudaGetSymbolAddress((void**)&wph, g_wp_hi);
    cudaGetSymbolAddress((void**)&wpl, g_wp_lo);
    cudaGetSymbolAddress((void**)&yh,  g_y_hi);
    cudaGetSymbolAddress((void**)&yl,  g_y_lo);

    cudaFuncSetAttribute(gemm_mma, cudaFuncAttributeMaxDynamicSharedMemorySize, GEMM_SMEM);
    cudaFuncSetAttribute(attn_fused, cudaFuncAttributeMaxDynamicSharedMemorySize, ATTN_SMEM);

    // Split inputs to bf16 hi/lo
    {
        int n4;
        n4 = M_ * C_ / 4;   split_bf16<<<(n4 + 255) / 256, 256>>>(x,      xh,  xl,  n4);
        n4 = C3_ * C_ / 4;  split_bf16<<<(n4 + 255) / 256, 256>>>(w_attn, wah, wal, n4);
        n4 = C_ * C_ / 4;   split_bf16<<<(n4 + 255) / 256, 256>>>(w_proj, wph, wpl, n4);
    }

    // 1) QKV projection (HMMA tensor cores)
    {
        dim3 grid(C3_ / 128, M_ / 128);
        gemm_mma<<<grid, 256, GEMM_SMEM>>>(xh, xl, wah, wal, b_attn, qkv, M_, C3_, C_);
    }

    // 2) Fused causal attention -> g_y
    {
        dim3 grid(T_ / 64, B_ * H_);
        attn_fused<<<grid, 256, ATTN_SMEM>>>(qkv, yb);
    }

    // Split attention output
    {
        int n4 = M_ * C_ / 4;
        split_bf16<<<(n4 + 255) / 256, 256>>>(yb, yh, yl, n4);
    }

    // 3) Output projection (HMMA tensor cores)
    {
        dim3 grid(C_ / 128, M_ / 128);
        gemm_mma<<<grid, 256, GEMM_SMEM>>>(yh, yl, wph, wpl, b_proj, out, M_, C_, C_);
    }
}

// round 4
// speedup vs baseline: 2.4350x; 1.7521x over previous
#include <cuda_runtime.h>
#include <cuda_bf16.h>
#include <cstdint>

// Problem constants
constexpr int B_  = 2;
constexpr int T_  = 2048;
constexpr int C_  = 1024;
constexpr int H_  = 16;
constexpr int D_  = 64;
constexpr int C3_ = 3 * C_;   // 3072
constexpr int M_  = B_ * T_;  // 4096

// Scratch (allocation-free rule: __device__ globals)
__device__ __nv_bfloat16 g_x_hi  [(size_t)M_  * C_];
__device__ __nv_bfloat16 g_x_lo  [(size_t)M_  * C_];
__device__ __nv_bfloat16 g_wa_hi [(size_t)C3_ * C_];
__device__ __nv_bfloat16 g_wa_lo [(size_t)C3_ * C_];
__device__ __nv_bfloat16 g_wp_hi [(size_t)C_  * C_];
__device__ __nv_bfloat16 g_wp_lo [(size_t)C_  * C_];
__device__ __nv_bfloat16 g_qkv_hi[(size_t)M_  * C3_];
__device__ __nv_bfloat16 g_qkv_lo[(size_t)M_  * C3_];
__device__ __nv_bfloat16 g_y_hi  [(size_t)M_  * C_];
__device__ __nv_bfloat16 g_y_lo  [(size_t)M_  * C_];

// ---------------------------------------------------------------------------
// Baseline-PTX helpers (sm_80+ only)
// ---------------------------------------------------------------------------
__device__ __forceinline__ uint32_t smem_u32(const void* p) {
    uint32_t a;
    asm("{ .reg .u64 t; cvta.to.shared.u64 t, %1; cvt.u32.u64 %0, t; }"
        : "=r"(a) : "l"(p));
    return a;
}
__device__ __forceinline__ void cp_async16(uint32_t saddr, const void* gaddr) {
    asm volatile("cp.async.cg.shared.global [%0], [%1], 16;"
                 :: "r"(saddr), "l"(gaddr) : "memory");
}
__device__ __forceinline__ void cp_commit() {
    asm volatile("cp.async.commit_group;" ::: "memory");
}
template <int N>
__device__ __forceinline__ void cp_wait() {
    asm volatile("cp.async.wait_group %0;" :: "n"(N) : "memory");
}
__device__ __forceinline__ void ldsm_x4(uint32_t& r0, uint32_t& r1,
                                        uint32_t& r2, uint32_t& r3, uint32_t addr) {
    asm volatile("ldmatrix.sync.aligned.m8n8.x4.shared.b16 {%0,%1,%2,%3}, [%4];"
                 : "=r"(r0), "=r"(r1), "=r"(r2), "=r"(r3) : "r"(addr));
}
__device__ __forceinline__ void ldsm_x4_t(uint32_t& r0, uint32_t& r1,
                                          uint32_t& r2, uint32_t& r3, uint32_t addr) {
    asm volatile("ldmatrix.sync.aligned.m8n8.x4.trans.shared.b16 {%0,%1,%2,%3}, [%4];"
                 : "=r"(r0), "=r"(r1), "=r"(r2), "=r"(r3) : "r"(addr));
}
__device__ __forceinline__ void mma16816(float* d, const uint32_t* a, const uint32_t* b) {
    asm volatile(
        "mma.sync.aligned.m16n8k16.row.col.f32.bf16.bf16.f32 "
        "{%0,%1,%2,%3}, {%4,%5,%6,%7}, {%8,%9}, {%0,%1,%2,%3};"
        : "+f"(d[0]), "+f"(d[1]), "+f"(d[2]), "+f"(d[3])
        : "r"(a[0]), "r"(a[1]), "r"(a[2]), "r"(a[3]), "r"(b[0]), "r"(b[1]));
}
// Split two fp32 into packed bf16x2 hi + bf16x2 lo (element 0 in low half)
__device__ __forceinline__ void split2(float v0, float v1, uint32_t& hi, uint32_t& lo) {
    __nv_bfloat16 h0 = __float2bfloat16(v0), h1 = __float2bfloat16(v1);
    __nv_bfloat16 l0 = __float2bfloat16(v0 - __bfloat162float(h0));
    __nv_bfloat16 l1 = __float2bfloat16(v1 - __bfloat162float(h1));
    __nv_bfloat162 Hv(h0, h1), Lv(l0, l1);
    hi = *(uint32_t*)&Hv; lo = *(uint32_t*)&Lv;
}

// ---------------------------------------------------------------------------
// fp32 -> bf16 hi/lo split
// ---------------------------------------------------------------------------
__global__ __launch_bounds__(256)
void split_bf16(const float* __restrict__ in, __nv_bfloat16* __restrict__ hi,
                __nv_bfloat16* __restrict__ lo, int n4)
{
    int i = blockIdx.x * blockDim.x + threadIdx.x;
    if (i >= n4) return;
    float4 v = ((const float4*)in)[i];
    uint32_t h01, l01, h23, l23;
    split2(v.x, v.y, h01, l01);
    split2(v.z, v.w, h23, l23);
    ((uint32_t*)hi)[2 * i + 0] = h01; ((uint32_t*)hi)[2 * i + 1] = h23;
    ((uint32_t*)lo)[2 * i + 0] = l01; ((uint32_t*)lo)[2 * i + 1] = l23;
}

// ---------------------------------------------------------------------------
// HMMA GEMM (NT): C[m,n] = sum_k A[m,k]*B[n,k] + bias[n]  (fp32 via bf16 split).
// OUTMODE 0: fp32 C. OUTMODE 1: bf16 hi/lo split C.
// CTA 128x128, BK=32, 8 warps (2x4), warp tile 64x32, cp.async double buffer.
// ---------------------------------------------------------------------------
constexpr int BK_   = 32;
constexpr int SKS_  = 40;
constexpr int MAT_E = 128 * SKS_;
constexpr int STAGE_E = 4 * MAT_E;
constexpr int GEMM_SMEM = 2 * STAGE_E * 2;

__device__ __forceinline__ void stage_loads(uint32_t sbuf,
    const __nv_bfloat16* Ahi, const __nv_bfloat16* Alo,
    const __nv_bfloat16* Bhi, const __nv_bfloat16* Blo,
    int bm, int bn, int k0, int K, int tid)
{
    const __nv_bfloat16* srcs[4] = { Ahi, Alo, Bhi, Blo };
    const int r0s[4] = { bm, bm, bn, bn };
#pragma unroll
    for (int m = 0; m < 4; m++) {
        uint32_t mbase = sbuf + m * MAT_E * 2;
#pragma unroll
        for (int j = 0; j < 2; j++) {
            int s   = tid + j * 256;
            int row = s >> 2;
            int cb  = (s & 3) * 8;
            const void* g = srcs[m] + (size_t)(r0s[m] + row) * K + k0 + cb;
            cp_async16(mbase + (row * SKS_ + cb) * 2, g);
        }
    }
    cp_commit();
}

template <int OUTMODE>
__global__ __launch_bounds__(256, 1)
void gemm_mma(const __nv_bfloat16* __restrict__ Ahi, const __nv_bfloat16* __restrict__ Alo,
              const __nv_bfloat16* __restrict__ Bhi, const __nv_bfloat16* __restrict__ Blo,
              const float* __restrict__ bias, float* __restrict__ Cf,
              __nv_bfloat16* __restrict__ Chi, __nv_bfloat16* __restrict__ Clo,
              int M, int N, int K)
{
    extern __shared__ __align__(128) __nv_bfloat16 smem[];
    const int tid  = threadIdx.x;
    const int wid  = tid >> 5;
    const int lane = tid & 31;
    const int wm   = wid >> 2;
    const int wn   = wid & 3;
    const int bm   = blockIdx.y * 128;
    const int bn   = blockIdx.x * 128;
    const uint32_t sbase = smem_u32(smem);

    float acc[4][4][4];
#pragma unroll
    for (int i = 0; i < 4; i++)
#pragma unroll
        for (int j = 0; j < 4; j++)
#pragma unroll
            for (int r = 0; r < 4; r++) acc[i][j][r] = 0.f;

    const int a_row = wm * 64 + (lane & 15);
    const int a_col = (lane >> 4) * 8;
    const int b_row = wn * 32 + ((lane >> 4) & 1) * 8 + (lane & 7);
    const int b_col = ((lane >> 3) & 1) * 8;

    const int S = K / BK_;
    stage_loads(sbase, Ahi, Alo, Bhi, Blo, bm, bn, 0, K, tid);

    for (int s = 0; s < S; s++) {
        if (s + 1 < S)
            stage_loads(sbase + ((s + 1) & 1) * STAGE_E * 2,
                        Ahi, Alo, Bhi, Blo, bm, bn, (s + 1) * BK_, K, tid);
        if (s + 1 < S) cp_wait<1>(); else cp_wait<0>();
        __syncthreads();

        const uint32_t sb  = sbase + (s & 1) * STAGE_E * 2;
        const uint32_t sAh = sb;
        const uint32_t sAl = sb + MAT_E * 2;
        const uint32_t sBh = sb + 2 * MAT_E * 2;
        const uint32_t sBl = sb + 3 * MAT_E * 2;

#pragma unroll
        for (int ks = 0; ks < 2; ks++) {
            uint32_t ah[4][4], al[4][4], bh[2][4], bl[2][4];
            const int ac = a_col + ks * 16;
            const int bc = b_col + ks * 16;
#pragma unroll
            for (int mt = 0; mt < 4; mt++) {
                uint32_t ra = ((a_row + mt * 16) * SKS_ + ac) * 2;
                ldsm_x4(ah[mt][0], ah[mt][1], ah[mt][2], ah[mt][3], sAh + ra);
                ldsm_x4(al[mt][0], al[mt][1], al[mt][2], al[mt][3], sAl + ra);
            }
#pragma unroll
            for (int np = 0; np < 2; np++) {
                uint32_t rb = ((b_row + np * 16) * SKS_ + bc) * 2;
                ldsm_x4(bh[np][0], bh[np][1], bh[np][2], bh[np][3], sBh + rb);
                ldsm_x4(bl[np][0], bl[np][1], bl[np][2], bl[np][3], sBl + rb);
            }
#pragma unroll
            for (int mt = 0; mt < 4; mt++)
#pragma unroll
                for (int nt = 0; nt < 4; nt++) {
                    const uint32_t* bhp = &bh[nt >> 1][(nt & 1) * 2];
                    const uint32_t* blp = &bl[nt >> 1][(nt & 1) * 2];
                    mma16816(acc[mt][nt], ah[mt], bhp);
                    mma16816(acc[mt][nt], ah[mt], blp);
                    mma16816(acc[mt][nt], al[mt], bhp);
                }
        }
        __syncthreads();
    }

    const int er = lane >> 2;
    const int ec = (lane & 3) * 2;
#pragma unroll
    for (int mt = 0; mt < 4; mt++) {
        const int row0 = bm + wm * 64 + mt * 16 + er;
#pragma unroll
        for (int nt = 0; nt < 4; nt++) {
            const int col = bn + wn * 32 + nt * 8 + ec;
            const float bx = bias[col], by = bias[col + 1];
            float v0 = acc[mt][nt][0] + bx, v1 = acc[mt][nt][1] + by;
            float v2 = acc[mt][nt][2] + bx, v3 = acc[mt][nt][3] + by;
            if (OUTMODE == 0) {
                *(float2*)(Cf + (size_t)row0 * N + col)       = make_float2(v0, v1);
                *(float2*)(Cf + (size_t)(row0 + 8) * N + col) = make_float2(v2, v3);
            } else {
                uint32_t uh, ul;
                split2(v0, v1, uh, ul);
                *(uint32_t*)(Chi + (size_t)row0 * N + col) = uh;
                *(uint32_t*)(Clo + (size_t)row0 * N + col) = ul;
                split2(v2, v3, uh, ul);
                *(uint32_t*)(Chi + (size_t)(row0 + 8) * N + col) = uh;
                *(uint32_t*)(Clo + (size_t)(row0 + 8) * N + col) = ul;
            }
        }
    }
}

// ---------------------------------------------------------------------------
// HMMA causal flash attention (bf16 hi/lo split, fp32 softmax/accum).
// CTA: 128 q-rows x (b,h). 8 warps x 16 rows. 64-key blocks, double buffered.
// ---------------------------------------------------------------------------
constexpr int SKA_    = 72;                    // padded bf16 row stride (144B)
constexpr int QTILE_E = 128 * SKA_;            // 9216
constexpr int KTILE_E = 64 * SKA_;             // 4608
constexpr int ATT_STAGE_E = 4 * KTILE_E;       // Kh,Kl,Vh,Vl
constexpr int ATT_SMEM = (2 * QTILE_E + 2 * ATT_STAGE_E) * 2;  // 110592 B

__device__ __forceinline__ void stage_kv(uint32_t sbuf,
    const __nv_bfloat16* qh, const __nv_bfloat16* ql,
    size_t bbase, int colK, int colV, int j0, int tid)
{
#pragma unroll
    for (int it = 0; it < 2; it++) {
        int s   = tid + it * 256;
        int row = s >> 3;
        int ch  = (s & 7) * 8;
        size_t g = bbase + (size_t)(j0 + row) * C3_;
        uint32_t so = (row * SKA_ + ch) * 2;
        cp_async16(sbuf + 0 * KTILE_E * 2 + so, qh + g + colK + ch);
        cp_async16(sbuf + 1 * KTILE_E * 2 + so, ql + g + colK + ch);
        cp_async16(sbuf + 2 * KTILE_E * 2 + so, qh + g + colV + ch);
        cp_async16(sbuf + 3 * KTILE_E * 2 + so, ql + g + colV + ch);
    }
}

__global__ __launch_bounds__(256, 1)
void attn_mma(const __nv_bfloat16* __restrict__ qvh, const __nv_bfloat16* __restrict__ qvl,
              __nv_bfloat16* __restrict__ yh, __nv_bfloat16* __restrict__ yl)
{
    extern __shared__ __align__(128) __nv_bfloat16 asm_[];
    const int tid  = threadIdx.x;
    const int wid  = tid >> 5;
    const int lane = tid & 31;
    const int qb = (int)gridDim.x - 1 - (int)blockIdx.x;
    const int bh = blockIdx.y;
    const int b  = bh >> 4;
    const int h  = bh & 15;
    const int q0 = qb * 128;
    const size_t bbase = (size_t)b * T_ * C3_;
    const int colQ = h * D_, colK = C_ + h * D_, colV = 2 * C_ + h * D_;

    const uint32_t sQh = smem_u32(asm_);
    const uint32_t sQl = sQh + QTILE_E * 2;
    const uint32_t sSt = sQl + QTILE_E * 2;

    // Prologue: Q (hi+lo) + KV block 0, one cp group
#pragma unroll
    for (int it = 0; it < 4; it++) {
        int s   = tid + it * 256;
        int row = s >> 3;
        int ch  = (s & 7) * 8;
        size_t g = bbase + (size_t)(q0 + row) * C3_ + colQ + ch;
        uint32_t so = (row * SKA_ + ch) * 2;
        cp_async16(sQh + so, qvh + g);
        cp_async16(sQl + so, qvl + g);
    }
    stage_kv(sSt, qvh, qvl, bbase, colK, colV, 0, tid);
    cp_commit();

    uint32_t aqh[4][4], aql[4][4];
    float oc[8][4];
#pragma unroll
    for (int i = 0; i < 8; i++)
#pragma unroll
        for (int j = 0; j < 4; j++) oc[i][j] = 0.f;
    float mrow[2] = { -1e30f, -1e30f };
    float lrow[2] = { 0.f, 0.f };

    const float scl = 0.125f * 1.4426950408889634f;
    const int nb = 2 * qb + 2;
    const int wrow0 = q0 + 16 * wid;           // warp's first q row (global)

    for (int j = 0; j < nb; j++) {
        if (j + 1 < nb) {
            stage_kv(sSt + ((j + 1) & 1) * ATT_STAGE_E * 2,
                     qvh, qvl, bbase, colK, colV, (j + 1) * 64, tid);
            cp_commit();
        }
        if (j + 1 < nb) cp_wait<1>(); else cp_wait<0>();
        __syncthreads();

        if (j == 0) {
            // Load Q fragments once (Q arrived with group 0)
#pragma unroll
            for (int kc = 0; kc < 4; kc++) {
                uint32_t ra = (((16 * wid) + (lane & 15)) * SKA_
                               + (lane >> 4) * 8 + kc * 16) * 2;
                ldsm_x4(aqh[kc][0], aqh[kc][1], aqh[kc][2], aqh[kc][3], sQh + ra);
                ldsm_x4(aql[kc][0], aql[kc][1], aql[kc][2], aql[kc][3], sQl + ra);
            }
        }

        const int j0 = j * 64;
        if (j0 <= wrow0 + 15) {                // warp has unmasked work
            const uint32_t sb  = sSt + (j & 1) * ATT_STAGE_E * 2;
            const uint32_t sKh = sb;
            const uint32_t sKl = sb + 1 * KTILE_E * 2;
            const uint32_t sVh = sb + 2 * KTILE_E * 2;
            const uint32_t sVl = sb + 3 * KTILE_E * 2;

            // ---- S = Q K^T (3-product split) ----
            float sc[8][4];
#pragma unroll
            for (int i = 0; i < 8; i++)
#pragma unroll
                for (int e = 0; e < 4; e++) sc[i][e] = 0.f;

#pragma unroll
            for (int kc = 0; kc < 4; kc++) {
                uint32_t kbh[4][4], kbl[4][4];
#pragma unroll
                for (int g = 0; g < 4; g++) {
                    int br = g * 16 + ((lane >> 4) & 1) * 8 + (lane & 7);
                    int bc = ((lane >> 3) & 1) * 8 + kc * 16;
                    uint32_t off = (br * SKA_ + bc) * 2;
                    ldsm_x4(kbh[g][0], kbh[g][1], kbh[g][2], kbh[g][3], sKh + off);
                    ldsm_x4(kbl[g][0], kbl[g][1], kbl[g][2], kbl[g][3], sKl + off);
                }
#pragma unroll
                for (int nt = 0; nt < 8; nt++) {
                    const uint32_t* bp_h = &kbh[nt >> 1][(nt & 1) * 2];
                    const uint32_t* bp_l = &kbl[nt >> 1][(nt & 1) * 2];
                    mma16816(sc[nt], aqh[kc], bp_h);
                    mma16816(sc[nt], aqh[kc], bp_l);
                    mma16816(sc[nt], aql[kc], bp_h);
                }
            }

            // ---- scale + causal mask ----
            const bool anymask = (j0 + 63 > wrow0);
            const int r0g = wrow0 + (lane >> 2);
#pragma unroll
            for (int nt = 0; nt < 8; nt++)
#pragma unroll
                for (int e = 0; e < 4; e++) {
                    float v = sc[nt][e] * scl;
                    if (anymask) {
                        int key = j0 + nt * 8 + (lane & 3) * 2 + (e & 1);
                        int row = r0g + (e >> 1) * 8;
                        if (key > row) v = -1e30f;
                    }
                    sc[nt][e] = v;
                }

            // ---- online softmax (per row-half rr: regs 2rr, 2rr+1) ----
#pragma unroll
            for (int rr = 0; rr < 2; rr++) {
                float mx = -1e30f;
#pragma unroll
                for (int nt = 0; nt < 8; nt++)
                    mx = fmaxf(mx, fmaxf(sc[nt][2 * rr], sc[nt][2 * rr + 1]));
                mx = fmaxf(mx, __shfl_xor_sync(0xffffffffu, mx, 1));
                mx = fmaxf(mx, __shfl_xor_sync(0xffffffffu, mx, 2));
                float mnew = fmaxf(mrow[rr], mx);
                float al   = exp2f(mrow[rr] - mnew);
                mrow[rr] = mnew;
                float rs = 0.f;
#pragma unroll
                for (int nt = 0; nt < 8; nt++) {
                    float p0 = exp2f(sc[nt][2 * rr]     - mnew);
                    float p1 = exp2f(sc[nt][2 * rr + 1] - mnew);
                    sc[nt][2 * rr] = p0; sc[nt][2 * rr + 1] = p1;
                    rs += p0 + p1;
                }
                rs += __shfl_xor_sync(0xffffffffu, rs, 1);
                rs += __shfl_xor_sync(0xffffffffu, rs, 2);
                lrow[rr] = lrow[rr] * al + rs;
#pragma unroll
                for (int nd = 0; nd < 8; nd++) {
                    oc[nd][2 * rr]     *= al;
                    oc[nd][2 * rr + 1] *= al;
                }
            }

            // ---- O += P V (P split hi/lo, V split hi/lo: 3 products) ----
#pragma unroll
            for (int t = 0; t < 4; t++) {
                uint32_t ph[4], pl[4];
                split2(sc[2 * t][0],     sc[2 * t][1],     ph[0], pl[0]);
                split2(sc[2 * t][2],     sc[2 * t][3],     ph[1], pl[1]);
                split2(sc[2 * t + 1][0], sc[2 * t + 1][1], ph[2], pl[2]);
                split2(sc[2 * t + 1][2], sc[2 * t + 1][3], ph[3], pl[3]);
                const int vkey = 16 * t + ((lane >> 3) & 1) * 8 + (lane & 7);
#pragma unroll
                for (int nd2 = 0; nd2 < 4; nd2++) {
                    uint32_t vfh[4], vfl[4];
                    uint32_t off = (vkey * SKA_ + nd2 * 16 + (lane >> 4) * 8) * 2;
                    ldsm_x4_t(vfh[0], vfh[1], vfh[2], vfh[3], sVh + off);
                    ldsm_x4_t(vfl[0], vfl[1], vfl[2], vfl[3], sVl + off);
                    mma16816(oc[2 * nd2],     ph, &vfh[0]);
                    mma16816(oc[2 * nd2],     ph, &vfl[0]);
                    mma16816(oc[2 * nd2],     pl, &vfh[0]);
                    mma16816(oc[2 * nd2 + 1], ph, &vfh[2]);
                    mma16816(oc[2 * nd2 + 1], ph, &vfl[2]);
                    mma16816(oc[2 * nd2 + 1], pl, &vfh[2]);
                }
            }
        }
        __syncthreads();
    }

    // ---- epilogue: normalize, split to bf16 hi/lo, store ----
    const float inv0 = 1.0f / lrow[0];
    const float inv1 = 1.0f / lrow[1];
    const int gr0 = wrow0 + (lane >> 2);
    const int gr1 = gr0 + 8;
    const int colb = h * D_ + (lane & 3) * 2;
#pragma unroll
    for (int nd = 0; nd < 8; nd++) {
        const int col = colb + nd * 8;
        uint32_t uh, ul;
        split2(oc[nd][0] * inv0, oc[nd][1] * inv0, uh, ul);
        *(uint32_t*)(yh + ((size_t)b * T_ + gr0) * C_ + col) = uh;
        *(uint32_t*)(yl + ((size_t)b * T_ + gr0) * C_ + col) = ul;
        split2(oc[nd][2] * inv1, oc[nd][3] * inv1, uh, ul);
        *(uint32_t*)(yh + ((size_t)b * T_ + gr1) * C_ + col) = uh;
        *(uint32_t*)(yl + ((size_t)b * T_ + gr1) * C_ + col) = ul;
    }
}

// ---------------------------------------------------------------------------
extern "C" void kernel_launch(void* const* d_in, const int* in_sizes, int n_in,
                              void* d_out, int out_size)
{
    const float* x      = (const float*)d_in[0];
    const float* w_attn = (const float*)d_in[1];
    const float* b_attn = (const float*)d_in[2];
    const float* w_proj = (const float*)d_in[3];
    const float* b_proj = (const float*)d_in[4];
    float* out = (float*)d_out;

    __nv_bfloat16 *xh, *xl, *wah, *wal, *wph, *wpl, *qh, *ql, *yh, *yl;
    cudaGetSymbolAddress((void**)&xh,  g_x_hi);
    cudaGetSymbolAddress((void**)&xl,  g_x_lo);
    cudaGetSymbolAddress((void**)&wah, g_wa_hi);
    cudaGetSymbolAddress((void**)&wal, g_wa_lo);
    cudaGetSymbolAddress((void**)&wph, g_wp_hi);
    cudaGetSymbolAddress((void**)&wpl, g_wp_lo);
    cudaGetSymbolAddress((void**)&qh,  g_qkv_hi);
    cudaGetSymbolAddress((void**)&ql,  g_qkv_lo);
    cudaGetSymbolAddress((void**)&yh,  g_y_hi);
    cudaGetSymbolAddress((void**)&yl,  g_y_lo);

    cudaFuncSetAttribute(gemm_mma<0>, cudaFuncAttributeMaxDynamicSharedMemorySize, GEMM_SMEM);
    cudaFuncSetAttribute(gemm_mma<1>, cudaFuncAttributeMaxDynamicSharedMemorySize, GEMM_SMEM);
    cudaFuncSetAttribute(attn_mma,    cudaFuncAttributeMaxDynamicSharedMemorySize, ATT_SMEM);

    // Split fp32 inputs to bf16 hi/lo
    {
        int n4;
        n4 = M_ * C_ / 4;   split_bf16<<<(n4 + 255) / 256, 256>>>(x,      xh,  xl,  n4);
        n4 = C3_ * C_ / 4;  split_bf16<<<(n4 + 255) / 256, 256>>>(w_attn, wah, wal, n4);
        n4 = C_ * C_ / 4;   split_bf16<<<(n4 + 255) / 256, 256>>>(w_proj, wph, wpl, n4);
    }

    // 1) QKV projection -> bf16 hi/lo qkv
    {
        dim3 grid(C3_ / 128, M_ / 128);
        gemm_mma<1><<<grid, 256, GEMM_SMEM>>>(xh, xl, wah, wal, b_attn,
                                              nullptr, qh, ql, M_, C3_, C_);
    }

    // 2) HMMA causal flash attention -> bf16 hi/lo y
    {
        dim3 grid(T_ / 128, B_ * H_);
        attn_mma<<<grid, 256, ATT_SMEM>>>(qh, ql, yh, yl);
    }

    // 3) Output projection -> fp32 out
    {
        dim3 grid(C_ / 128, M_ / 128);
        gemm_mma<0><<<grid, 256, GEMM_SMEM>>>(yh, yl, wph, wpl, b_proj,
                                              out, nullptr, nullptr, M_, C_, C_);
    }
}

// round 5
// speedup vs baseline: 2.4872x; 1.0214x over previous
#include <cuda_runtime.h>
#include <cuda_bf16.h>
#include <cstdint>

// Problem constants
constexpr int B_  = 2;
constexpr int T_  = 2048;
constexpr int C_  = 1024;
constexpr int H_  = 16;
constexpr int D_  = 64;
constexpr int C3_ = 3 * C_;   // 3072
constexpr int M_  = B_ * T_;  // 4096

// Scratch (allocation-free rule: __device__ globals)
__device__ __nv_bfloat16 g_x_hi  [(size_t)M_  * C_];
__device__ __nv_bfloat16 g_x_lo  [(size_t)M_  * C_];
__device__ __nv_bfloat16 g_wa_hi [(size_t)C3_ * C_];
__device__ __nv_bfloat16 g_wa_lo [(size_t)C3_ * C_];
__device__ __nv_bfloat16 g_wp_hi [(size_t)C_  * C_];
__device__ __nv_bfloat16 g_wp_lo [(size_t)C_  * C_];
__device__ __nv_bfloat16 g_qkv_hi[(size_t)M_  * C3_];
__device__ __nv_bfloat16 g_qkv_lo[(size_t)M_  * C3_];
__device__ __nv_bfloat16 g_y_hi  [(size_t)M_  * C_];
__device__ __nv_bfloat16 g_y_lo  [(size_t)M_  * C_];

// ---------------------------------------------------------------------------
// Baseline-PTX helpers (sm_80+ only)
// ---------------------------------------------------------------------------
__device__ __forceinline__ uint32_t smem_u32(const void* p) {
    uint32_t a;
    asm("{ .reg .u64 t; cvta.to.shared.u64 t, %1; cvt.u32.u64 %0, t; }"
        : "=r"(a) : "l"(p));
    return a;
}
__device__ __forceinline__ void cp_async16(uint32_t saddr, const void* gaddr) {
    asm volatile("cp.async.cg.shared.global [%0], [%1], 16;"
                 :: "r"(saddr), "l"(gaddr) : "memory");
}
__device__ __forceinline__ void cp_commit() {
    asm volatile("cp.async.commit_group;" ::: "memory");
}
template <int N>
__device__ __forceinline__ void cp_wait() {
    asm volatile("cp.async.wait_group %0;" :: "n"(N) : "memory");
}
__device__ __forceinline__ void ldsm_x4(uint32_t& r0, uint32_t& r1,
                                        uint32_t& r2, uint32_t& r3, uint32_t addr) {
    asm volatile("ldmatrix.sync.aligned.m8n8.x4.shared.b16 {%0,%1,%2,%3}, [%4];"
                 : "=r"(r0), "=r"(r1), "=r"(r2), "=r"(r3) : "r"(addr));
}
__device__ __forceinline__ void ldsm_x4_t(uint32_t& r0, uint32_t& r1,
                                          uint32_t& r2, uint32_t& r3, uint32_t addr) {
    asm volatile("ldmatrix.sync.aligned.m8n8.x4.trans.shared.b16 {%0,%1,%2,%3}, [%4];"
                 : "=r"(r0), "=r"(r1), "=r"(r2), "=r"(r3) : "r"(addr));
}
__device__ __forceinline__ void mma16816(float* d, const uint32_t* a, const uint32_t* b) {
    asm volatile(
        "mma.sync.aligned.m16n8k16.row.col.f32.bf16.bf16.f32 "
        "{%0,%1,%2,%3}, {%4,%5,%6,%7}, {%8,%9}, {%0,%1,%2,%3};"
        : "+f"(d[0]), "+f"(d[1]), "+f"(d[2]), "+f"(d[3])
        : "r"(a[0]), "r"(a[1]), "r"(a[2]), "r"(a[3]), "r"(b[0]), "r"(b[1]));
}
__device__ __forceinline__ void split2(float v0, float v1, uint32_t& hi, uint32_t& lo) {
    __nv_bfloat16 h0 = __float2bfloat16(v0), h1 = __float2bfloat16(v1);
    __nv_bfloat16 l0 = __float2bfloat16(v0 - __bfloat162float(h0));
    __nv_bfloat16 l1 = __float2bfloat16(v1 - __bfloat162float(h1));
    __nv_bfloat162 Hv(h0, h1), Lv(l0, l1);
    hi = *(uint32_t*)&Hv; lo = *(uint32_t*)&Lv;
}

// ---------------------------------------------------------------------------
// fp32 -> bf16 hi/lo split
// ---------------------------------------------------------------------------
__global__ __launch_bounds__(256)
void split_bf16(const float* __restrict__ in, __nv_bfloat16* __restrict__ hi,
                __nv_bfloat16* __restrict__ lo, int n4)
{
    int i = blockIdx.x * blockDim.x + threadIdx.x;
    if (i >= n4) return;
    float4 v = ((const float4*)in)[i];
    uint32_t h01, l01, h23, l23;
    split2(v.x, v.y, h01, l01);
    split2(v.z, v.w, h23, l23);
    ((uint32_t*)hi)[2 * i + 0] = h01; ((uint32_t*)hi)[2 * i + 1] = h23;
    ((uint32_t*)lo)[2 * i + 0] = l01; ((uint32_t*)lo)[2 * i + 1] = l23;
}

// ---------------------------------------------------------------------------
// HMMA GEMM (NT), 5-buffer cp.async ring (prefetch depth 4).
// CTA 128x128, BK=32, 8 warps (2x4), warp tile 64x32.
// ---------------------------------------------------------------------------
constexpr int BK_   = 32;
constexpr int SKS_  = 40;
constexpr int MAT_E = 128 * SKS_;
constexpr int STAGE_E = 4 * MAT_E;               // Ah, Al, Bh, Bl
constexpr int NBUF_G = 5;
constexpr int GEMM_SMEM = NBUF_G * STAGE_E * 2;  // 204800 B

// Issues one stage of loads and commits the group.
__device__ __forceinline__ void stage_loads(uint32_t sbuf,
    const __nv_bfloat16* Ahi, const __nv_bfloat16* Alo,
    const __nv_bfloat16* Bhi, const __nv_bfloat16* Blo,
    int bm, int bn, int k0, int K, int tid)
{
    const __nv_bfloat16* srcs[4] = { Ahi, Alo, Bhi, Blo };
    const int r0s[4] = { bm, bm, bn, bn };
#pragma unroll
    for (int m = 0; m < 4; m++) {
        uint32_t mbase = sbuf + m * MAT_E * 2;
#pragma unroll
        for (int j = 0; j < 2; j++) {
            int s   = tid + j * 256;
            int row = s >> 2;
            int cb  = (s & 3) * 8;
            const void* g = srcs[m] + (size_t)(r0s[m] + row) * K + k0 + cb;
            cp_async16(mbase + (row * SKS_ + cb) * 2, g);
        }
    }
    cp_commit();
}

template <int OUTMODE>
__global__ __launch_bounds__(256, 1)
void gemm_mma(const __nv_bfloat16* __restrict__ Ahi, const __nv_bfloat16* __restrict__ Alo,
              const __nv_bfloat16* __restrict__ Bhi, const __nv_bfloat16* __restrict__ Blo,
              const float* __restrict__ bias, float* __restrict__ Cf,
              __nv_bfloat16* __restrict__ Chi, __nv_bfloat16* __restrict__ Clo,
              int M, int N, int K)
{
    extern __shared__ __align__(128) __nv_bfloat16 smem[];
    const int tid  = threadIdx.x;
    const int wid  = tid >> 5;
    const int lane = tid & 31;
    const int wm   = wid >> 2;
    const int wn   = wid & 3;
    const int bm   = blockIdx.y * 128;
    const int bn   = blockIdx.x * 128;
    const uint32_t sbase = smem_u32(smem);

    float acc[4][4][4];
#pragma unroll
    for (int i = 0; i < 4; i++)
#pragma unroll
        for (int j = 0; j < 4; j++)
#pragma unroll
            for (int r = 0; r < 4; r++) acc[i][j][r] = 0.f;

    const int a_row = wm * 64 + (lane & 15);
    const int a_col = (lane >> 4) * 8;
    const int b_row = wn * 32 + ((lane >> 4) & 1) * 8 + (lane & 7);
    const int b_col = ((lane >> 3) & 1) * 8;

    const int S = K / BK_;   // 32

    // Prologue: prefetch stages 0..3
#pragma unroll
    for (int p = 0; p < 4; p++)
        stage_loads(sbase + p * STAGE_E * 2, Ahi, Alo, Bhi, Blo,
                    bm, bn, p * BK_, K, tid);

    int buf = 0, nbuf = 4 % NBUF_G;
    for (int s = 0; s < S; s++) {
        cp_wait<3>();            // stage s's group retired (3 newer remain)
        __syncthreads();         // data visible; all warps done with buf that s+4 will overwrite

        if (s + 4 < S)
            stage_loads(sbase + nbuf * STAGE_E * 2, Ahi, Alo, Bhi, Blo,
                        bm, bn, (s + 4) * BK_, K, tid);
        else
            cp_commit();         // empty group keeps the wait arithmetic exact

        const uint32_t sb  = sbase + buf * STAGE_E * 2;
        const uint32_t sAh = sb;
        const uint32_t sAl = sb + MAT_E * 2;
        const uint32_t sBh = sb + 2 * MAT_E * 2;
        const uint32_t sBl = sb + 3 * MAT_E * 2;

#pragma unroll
        for (int ks = 0; ks < 2; ks++) {
            uint32_t ah[4][4], al[4][4], bh[2][4], bl[2][4];
            const int ac = a_col + ks * 16;
            const int bc = b_col + ks * 16;
#pragma unroll
            for (int mt = 0; mt < 4; mt++) {
                uint32_t ra = ((a_row + mt * 16) * SKS_ + ac) * 2;
                ldsm_x4(ah[mt][0], ah[mt][1], ah[mt][2], ah[mt][3], sAh + ra);
                ldsm_x4(al[mt][0], al[mt][1], al[mt][2], al[mt][3], sAl + ra);
            }
#pragma unroll
            for (int np = 0; np < 2; np++) {
                uint32_t rb = ((b_row + np * 16) * SKS_ + bc) * 2;
                ldsm_x4(bh[np][0], bh[np][1], bh[np][2], bh[np][3], sBh + rb);
                ldsm_x4(bl[np][0], bl[np][1], bl[np][2], bl[np][3], sBl + rb);
            }
#pragma unroll
            for (int mt = 0; mt < 4; mt++)
#pragma unroll
                for (int nt = 0; nt < 4; nt++) {
                    const uint32_t* bhp = &bh[nt >> 1][(nt & 1) * 2];
                    const uint32_t* blp = &bl[nt >> 1][(nt & 1) * 2];
                    mma16816(acc[mt][nt], ah[mt], bhp);
                    mma16816(acc[mt][nt], ah[mt], blp);
                    mma16816(acc[mt][nt], al[mt], bhp);
                }
        }
        if (++buf == NBUF_G)  buf = 0;
        if (++nbuf == NBUF_G) nbuf = 0;
    }

    const int er = lane >> 2;
    const int ec = (lane & 3) * 2;
#pragma unroll
    for (int mt = 0; mt < 4; mt++) {
        const int row0 = bm + wm * 64 + mt * 16 + er;
#pragma unroll
        for (int nt = 0; nt < 4; nt++) {
            const int col = bn + wn * 32 + nt * 8 + ec;
            const float bx = bias[col], by = bias[col + 1];
            float v0 = acc[mt][nt][0] + bx, v1 = acc[mt][nt][1] + by;
            float v2 = acc[mt][nt][2] + bx, v3 = acc[mt][nt][3] + by;
            if (OUTMODE == 0) {
                *(float2*)(Cf + (size_t)row0 * N + col)       = make_float2(v0, v1);
                *(float2*)(Cf + (size_t)(row0 + 8) * N + col) = make_float2(v2, v3);
            } else {
                uint32_t uh, ul;
                split2(v0, v1, uh, ul);
                *(uint32_t*)(Chi + (size_t)row0 * N + col) = uh;
                *(uint32_t*)(Clo + (size_t)row0 * N + col) = ul;
                split2(v2, v3, uh, ul);
                *(uint32_t*)(Chi + (size_t)(row0 + 8) * N + col) = uh;
                *(uint32_t*)(Clo + (size_t)(row0 + 8) * N + col) = ul;
            }
        }
    }
}

// ---------------------------------------------------------------------------
// HMMA causal flash attention, 3-buffer KV ring (prefetch depth 2).
// CTA: 128 q-rows x (b,h). 8 warps x 16 rows. 64-key blocks.
// ---------------------------------------------------------------------------
constexpr int SKA_    = 72;
constexpr int QTILE_E = 128 * SKA_;
constexpr int KTILE_E = 64 * SKA_;
constexpr int ATT_STAGE_E = 4 * KTILE_E;          // Kh,Kl,Vh,Vl
constexpr int NBUF_A  = 3;
constexpr int ATT_SMEM = (2 * QTILE_E + NBUF_A * ATT_STAGE_E) * 2;  // 147456 B

// Issues one KV stage (no commit — caller commits so Q can share group 0).
__device__ __forceinline__ void stage_kv(uint32_t sbuf,
    const __nv_bfloat16* qh, const __nv_bfloat16* ql,
    size_t bbase, int colK, int colV, int j0, int tid)
{
#pragma unroll
    for (int it = 0; it < 2; it++) {
        int s   = tid + it * 256;
        int row = s >> 3;
        int ch  = (s & 7) * 8;
        size_t g = bbase + (size_t)(j0 + row) * C3_;
        uint32_t so = (row * SKA_ + ch) * 2;
        cp_async16(sbuf + 0 * KTILE_E * 2 + so, qh + g + colK + ch);
        cp_async16(sbuf + 1 * KTILE_E * 2 + so, ql + g + colK + ch);
        cp_async16(sbuf + 2 * KTILE_E * 2 + so, qh + g + colV + ch);
        cp_async16(sbuf + 3 * KTILE_E * 2 + so, ql + g + colV + ch);
    }
}

__global__ __launch_bounds__(256, 1)
void attn_mma(const __nv_bfloat16* __restrict__ qvh, const __nv_bfloat16* __restrict__ qvl,
              __nv_bfloat16* __restrict__ yh, __nv_bfloat16* __restrict__ yl)
{
    extern __shared__ __align__(128) __nv_bfloat16 asm_[];
    const int tid  = threadIdx.x;
    const int wid  = tid >> 5;
    const int lane = tid & 31;
    const int qb = (int)gridDim.x - 1 - (int)blockIdx.x;
    const int bh = blockIdx.y;
    const int b  = bh >> 4;
    const int h  = bh & 15;
    const int q0 = qb * 128;
    const size_t bbase = (size_t)b * T_ * C3_;
    const int colQ = h * D_, colK = C_ + h * D_, colV = 2 * C_ + h * D_;

    const uint32_t sQh = smem_u32(asm_);
    const uint32_t sQl = sQh + QTILE_E * 2;
    const uint32_t sSt = sQl + QTILE_E * 2;

    const int nb = 2 * qb + 2;

    // Prologue: Q + KV0 in group 0; KV1 in group 1.
#pragma unroll
    for (int it = 0; it < 4; it++) {
        int s   = tid + it * 256;
        int row = s >> 3;
        int ch  = (s & 7) * 8;
        size_t g = bbase + (size_t)(q0 + row) * C3_ + colQ + ch;
        uint32_t so = (row * SKA_ + ch) * 2;
        cp_async16(sQh + so, qvh + g);
        cp_async16(sQl + so, qvl + g);
    }
    stage_kv(sSt, qvh, qvl, bbase, colK, colV, 0, tid);
    cp_commit();
    if (1 < nb) stage_kv(sSt + ATT_STAGE_E * 2, qvh, qvl, bbase, colK, colV, 64, tid);
    cp_commit();

    uint32_t aqh[4][4], aql[4][4];
    float oc[8][4];
#pragma unroll
    for (int i = 0; i < 8; i++)
#pragma unroll
        for (int j = 0; j < 4; j++) oc[i][j] = 0.f;
    float mrow[2] = { -1e30f, -1e30f };
    float lrow[2] = { 0.f, 0.f };

    const float scl = 0.125f * 1.4426950408889634f;
    const int wrow0 = q0 + 16 * wid;

    int buf = 0, nbufi = 2;
    for (int j = 0; j < nb; j++) {
        cp_wait<1>();
        __syncthreads();

        if (j == 0) {
#pragma unroll
            for (int kc = 0; kc < 4; kc++) {
                uint32_t ra = (((16 * wid) + (lane & 15)) * SKA_
                               + (lane >> 4) * 8 + kc * 16) * 2;
                ldsm_x4(aqh[kc][0], aqh[kc][1], aqh[kc][2], aqh[kc][3], sQh + ra);
                ldsm_x4(aql[kc][0], aql[kc][1], aql[kc][2], aql[kc][3], sQl + ra);
            }
        }

        if (j + 2 < nb)
            stage_kv(sSt + nbufi * ATT_STAGE_E * 2, qvh, qvl,
                     bbase, colK, colV, (j + 2) * 64, tid);
        cp_commit();

        const int j0 = j * 64;
        if (j0 <= wrow0 + 15) {
            const uint32_t sb  = sSt + buf * ATT_STAGE_E * 2;
            const uint32_t sKh = sb;
            const uint32_t sKl = sb + 1 * KTILE_E * 2;
            const uint32_t sVh = sb + 2 * KTILE_E * 2;
            const uint32_t sVl = sb + 3 * KTILE_E * 2;

            // ---- S = Q K^T ----
            float sc[8][4];
#pragma unroll
            for (int i = 0; i < 8; i++)
#pragma unroll
                for (int e = 0; e < 4; e++) sc[i][e] = 0.f;

#pragma unroll
            for (int kc = 0; kc < 4; kc++) {
                uint32_t kbh[4][4], kbl[4][4];
#pragma unroll
                for (int g = 0; g < 4; g++) {
                    int br = g * 16 + ((lane >> 4) & 1) * 8 + (lane & 7);
                    int bc = ((lane >> 3) & 1) * 8 + kc * 16;
                    uint32_t off = (br * SKA_ + bc) * 2;
                    ldsm_x4(kbh[g][0], kbh[g][1], kbh[g][2], kbh[g][3], sKh + off);
                    ldsm_x4(kbl[g][0], kbl[g][1], kbl[g][2], kbl[g][3], sKl + off);
                }
#pragma unroll
                for (int nt = 0; nt < 8; nt++) {
                    const uint32_t* bp_h = &kbh[nt >> 1][(nt & 1) * 2];
                    const uint32_t* bp_l = &kbl[nt >> 1][(nt & 1) * 2];
                    mma16816(sc[nt], aqh[kc], bp_h);
                    mma16816(sc[nt], aqh[kc], bp_l);
                    mma16816(sc[nt], aql[kc], bp_h);
                }
            }

            // ---- scale + causal mask ----
            const bool anymask = (j0 + 63 > wrow0);
            const int r0g = wrow0 + (lane >> 2);
#pragma unroll
            for (int nt = 0; nt < 8; nt++)
#pragma unroll
                for (int e = 0; e < 4; e++) {
                    float v = sc[nt][e] * scl;
                    if (anymask) {
                        int key = j0 + nt * 8 + (lane & 3) * 2 + (e & 1);
                        int row = r0g + (e >> 1) * 8;
                        if (key > row) v = -1e30f;
                    }
                    sc[nt][e] = v;
                }

            // ---- online softmax ----
#pragma unroll
            for (int rr = 0; rr < 2; rr++) {
                float mx = -1e30f;
#pragma unroll
                for (int nt = 0; nt < 8; nt++)
                    mx = fmaxf(mx, fmaxf(sc[nt][2 * rr], sc[nt][2 * rr + 1]));
                mx = fmaxf(mx, __shfl_xor_sync(0xffffffffu, mx, 1));
                mx = fmaxf(mx, __shfl_xor_sync(0xffffffffu, mx, 2));
                float mnew = fmaxf(mrow[rr], mx);
                float al   = exp2f(mrow[rr] - mnew);
                mrow[rr] = mnew;
                float rs = 0.f;
#pragma unroll
                for (int nt = 0; nt < 8; nt++) {
                    float p0 = exp2f(sc[nt][2 * rr]     - mnew);
                    float p1 = exp2f(sc[nt][2 * rr + 1] - mnew);
                    sc[nt][2 * rr] = p0; sc[nt][2 * rr + 1] = p1;
                    rs += p0 + p1;
                }
                rs += __shfl_xor_sync(0xffffffffu, rs, 1);
                rs += __shfl_xor_sync(0xffffffffu, rs, 2);
                lrow[rr] = lrow[rr] * al + rs;
#pragma unroll
                for (int nd = 0; nd < 8; nd++) {
                    oc[nd][2 * rr]     *= al;
                    oc[nd][2 * rr + 1] *= al;
                }
            }

            // ---- O += P V ----
#pragma unroll
            for (int t = 0; t < 4; t++) {
                uint32_t ph[4], pl[4];
                split2(sc[2 * t][0],     sc[2 * t][1],     ph[0], pl[0]);
                split2(sc[2 * t][2],     sc[2 * t][3],     ph[1], pl[1]);
                split2(sc[2 * t + 1][0], sc[2 * t + 1][1], ph[2], pl[2]);
                split2(sc[2 * t + 1][2], sc[2 * t + 1][3], ph[3], pl[3]);
                const int vkey = 16 * t + ((lane >> 3) & 1) * 8 + (lane & 7);
#pragma unroll
                for (int nd2 = 0; nd2 < 4; nd2++) {
                    uint32_t vfh[4], vfl[4];
                    uint32_t off = (vkey * SKA_ + nd2 * 16 + (lane >> 4) * 8) * 2;
                    ldsm_x4_t(vfh[0], vfh[1], vfh[2], vfh[3], sVh + off);
                    ldsm_x4_t(vfl[0], vfl[1], vfl[2], vfl[3], sVl + off);
                    mma16816(oc[2 * nd2],     ph, &vfh[0]);
                    mma16816(oc[2 * nd2],     ph, &vfl[0]);
                    mma16816(oc[2 * nd2],     pl, &vfh[0]);
                    mma16816(oc[2 * nd2 + 1], ph, &vfh[2]);
                    mma16816(oc[2 * nd2 + 1], ph, &vfl[2]);
                    mma16816(oc[2 * nd2 + 1], pl, &vfh[2]);
                }
            }
        }
        if (++buf == NBUF_A)   buf = 0;
        if (++nbufi == NBUF_A) nbufi = 0;
    }

    // ---- epilogue ----
    const float inv0 = 1.0f / lrow[0];
    const float inv1 = 1.0f / lrow[1];
    const int gr0 = wrow0 + (lane >> 2);
    const int gr1 = gr0 + 8;
    const int colb = h * D_ + (lane & 3) * 2;
#pragma unroll
    for (int nd = 0; nd < 8; nd++) {
        const int col = colb + nd * 8;
        uint32_t uh, ul;
        split2(oc[nd][0] * inv0, oc[nd][1] * inv0, uh, ul);
        *(uint32_t*)(yh + ((size_t)b * T_ + gr0) * C_ + col) = uh;
        *(uint32_t*)(yl + ((size_t)b * T_ + gr0) * C_ + col) = ul;
        split2(oc[nd][2] * inv1, oc[nd][3] * inv1, uh, ul);
        *(uint32_t*)(yh + ((size_t)b * T_ + gr1) * C_ + col) = uh;
        *(uint32_t*)(yl + ((size_t)b * T_ + gr1) * C_ + col) = ul;
    }
}

// ---------------------------------------------------------------------------
extern "C" void kernel_launch(void* const* d_in, const int* in_sizes, int n_in,
                              void* d_out, int out_size)
{
    const float* x      = (const float*)d_in[0];
    const float* w_attn = (const float*)d_in[1];
    const float* b_attn = (const float*)d_in[2];
    const float* w_proj = (const float*)d_in[3];
    const float* b_proj = (const float*)d_in[4];
    float* out = (float*)d_out;

    __nv_bfloat16 *xh, *xl, *wah, *wal, *wph, *wpl, *qh, *ql, *yh, *yl;
    cudaGetSymbolAddress((void**)&xh,  g_x_hi);
    cudaGetSymbolAddress((void**)&xl,  g_x_lo);
    cudaGetSymbolAddress((void**)&wah, g_wa_hi);
    cudaGetSymbolAddress((void**)&wal, g_wa_lo);
    cudaGetSymbolAddress((void**)&wph, g_wp_hi);
    cudaGetSymbolAddress((void**)&wpl, g_wp_lo);
    cudaGetSymbolAddress((void**)&qh,  g_qkv_hi);
    cudaGetSymbolAddress((void**)&ql,  g_qkv_lo);
    cudaGetSymbolAddress((void**)&yh,  g_y_hi);
    cudaGetSymbolAddress((void**)&yl,  g_y_lo);

    cudaFuncSetAttribute(gemm_mma<0>, cudaFuncAttributeMaxDynamicSharedMemorySize, GEMM_SMEM);
    cudaFuncSetAttribute(gemm_mma<1>, cudaFuncAttributeMaxDynamicSharedMemorySize, GEMM_SMEM);
    cudaFuncSetAttribute(attn_mma,    cudaFuncAttributeMaxDynamicSharedMemorySize, ATT_SMEM);

    // Split fp32 inputs to bf16 hi/lo
    {
        int n4;
        n4 = M_ * C_ / 4;   split_bf16<<<(n4 + 255) / 256, 256>>>(x,      xh,  xl,  n4);
        n4 = C3_ * C_ / 4;  split_bf16<<<(n4 + 255) / 256, 256>>>(w_attn, wah, wal, n4);
        n4 = C_ * C_ / 4;   split_bf16<<<(n4 + 255) / 256, 256>>>(w_proj, wph, wpl, n4);
    }

    // 1) QKV projection -> bf16 hi/lo qkv
    {
        dim3 grid(C3_ / 128, M_ / 128);
        gemm_mma<1><<<grid, 256, GEMM_SMEM>>>(xh, xl, wah, wal, b_attn,
                                              nullptr, qh, ql, M_, C3_, C_);
    }

    // 2) HMMA causal flash attention -> bf16 hi/lo y
    {
        dim3 grid(T_ / 128, B_ * H_);
        attn_mma<<<grid, 256, ATT_SMEM>>>(qh, ql, yh, yl);
    }

    // 3) Output projection -> fp32 out
    {
        dim3 grid(C_ / 128, M_ / 128);
        gemm_mma<0><<<grid, 256, GEMM_SMEM>>>(yh, yl, wph, wpl, b_proj,
                                              out, nullptr, nullptr, M_, C_, C_);
    }
}